// round 5
// baseline (speedup 1.0000x reference)
#include <cuda_runtime.h>
#include <cstdint>

// Problem constants
static constexpr int O_DIM = 4096;     // out features (N)
static constexpr int I_DIM = 4096;     // in features (K)
static constexpr int M_DIM = 8 * 2048; // batch*seq (M)
static constexpr int R_DIM = 16;       // LoRA rank

static constexpr float QMAX = 16256.0f;   // 127 * 128

// Scratch (device globals — no allocation allowed)
__device__ __align__(16) int8_t g_X1[(size_t)M_DIM * I_DIM];
__device__ __align__(16) int8_t g_X2[(size_t)M_DIM * I_DIM];
__device__ __align__(16) int8_t g_W1[(size_t)O_DIM * I_DIM];
__device__ __align__(16) int8_t g_W2[(size_t)O_DIM * I_DIM];
__device__ float g_fx[M_DIM];
__device__ float g_fw[O_DIM];

// ---------------------------------------------------------------------------
__device__ __forceinline__ float blk_max(float v, int tid) {
    __shared__ float red[8];
#pragma unroll
    for (int off = 16; off; off >>= 1)
        v = fmaxf(v, __shfl_xor_sync(0xFFFFFFFFu, v, off));
    if ((tid & 31) == 0) red[tid >> 5] = v;
    __syncthreads();
    float m = red[0];
#pragma unroll
    for (int w = 1; w < 8; w++) m = fmaxf(m, red[w]);
    return m;
}

// Two-limb int8 quantization. NO char casts (aarch64 plain char is unsigned:
// float->char saturated negatives to 0 — the round-3/4 correctness bug).
// Packs 4 lanes into uint32 words via explicit signed-int byte masking.
__device__ __forceinline__ void quant4_pack(const float* vs, float s,
                                            uint32_t& p1, uint32_t& p2) {
    uint32_t r1 = 0, r2 = 0;
#pragma unroll
    for (int j = 0; j < 4; j++) {
        const float qf = vs[j] * s;
        int h = __float2int_rn(qf * (1.0f / 128.0f));
        h = max(-127, min(127, h));
        int l = __float2int_rn(qf - 128.0f * (float)h);
        l = max(-127, min(127, l));
        r1 |= ((uint32_t)h & 0xFFu) << (8 * j);
        r2 |= ((uint32_t)l & 0xFFu) << (8 * j);
    }
    p1 = r1; p2 = r2;
}

// ---------------------------------------------------------------------------
// Kernel 1: W row = scales*(q-128) + 0.5*up@down; per-row max; 2-limb int8.
// ---------------------------------------------------------------------------
__global__ void prep_w_kernel(const int* __restrict__ qw,
                              const float* __restrict__ scales,
                              const float* __restrict__ up,
                              const float* __restrict__ down) {
    const int o = blockIdx.x;
    const int tid = threadIdx.x;
    __shared__ float ws[I_DIM];
    __shared__ float up_s[R_DIM];
    if (tid < R_DIM) up_s[tid] = up[o * R_DIM + tid];
    __syncthreads();

    const int4* qrow = (const int4*)(qw + (size_t)o * I_DIM);
    float mx = 0.f;
    for (int i = tid; i < I_DIM / 4; i += blockDim.x) {
        const int4 q = qrow[i];
        const float sc = scales[o * (I_DIM / 32) + (i >> 3)];
        float l[4] = {0.f, 0.f, 0.f, 0.f};
#pragma unroll
        for (int r = 0; r < R_DIM; r++) {
            const float4 d4 = ((const float4*)(down + (size_t)r * I_DIM))[i];
            const float u = up_s[r];
            l[0] = fmaf(u, d4.x, l[0]); l[1] = fmaf(u, d4.y, l[1]);
            l[2] = fmaf(u, d4.z, l[2]); l[3] = fmaf(u, d4.w, l[3]);
        }
        float w[4];
        w[0] = fmaf(sc, (float)q.x - 128.f, 0.5f * l[0]);
        w[1] = fmaf(sc, (float)q.y - 128.f, 0.5f * l[1]);
        w[2] = fmaf(sc, (float)q.z - 128.f, 0.5f * l[2]);
        w[3] = fmaf(sc, (float)q.w - 128.f, 0.5f * l[3]);
        ((float4*)ws)[i] = make_float4(w[0], w[1], w[2], w[3]);
#pragma unroll
        for (int j = 0; j < 4; j++) mx = fmaxf(mx, fabsf(w[j]));
    }
    __syncthreads();
    mx = blk_max(mx, tid);
    const float s = (mx > 0.f) ? QMAX / mx : 0.f;
    if (tid == 0) g_fw[o] = (mx > 0.f) ? mx / QMAX : 0.f;

    for (int i = tid; i < I_DIM / 4; i += blockDim.x) {
        float v[4];
        *(float4*)v = ((const float4*)ws)[i];
        uint32_t p1, p2;
        quant4_pack(v, s, p1, p2);
        ((uint32_t*)g_W1)[(size_t)o * (I_DIM / 4) + i] = p1;
        ((uint32_t*)g_W2)[(size_t)o * (I_DIM / 4) + i] = p2;
    }
}

// ---------------------------------------------------------------------------
// Kernel 2: x rows -> per-row max -> 2-limb int8.
// ---------------------------------------------------------------------------
__global__ void prep_x_kernel(const float* __restrict__ x) {
    const int m = blockIdx.x;
    const int tid = threadIdx.x;
    __shared__ float xs[I_DIM];
    const float4* row = (const float4*)(x + (size_t)m * I_DIM);
    float mx = 0.f;
    for (int i = tid; i < I_DIM / 4; i += blockDim.x) {
        const float4 v = row[i];
        ((float4*)xs)[i] = v;
        mx = fmaxf(mx, fmaxf(fmaxf(fabsf(v.x), fabsf(v.y)),
                             fmaxf(fabsf(v.z), fabsf(v.w))));
    }
    __syncthreads();
    mx = blk_max(mx, tid);
    const float s = (mx > 0.f) ? QMAX / mx : 0.f;
    if (tid == 0) g_fx[m] = (mx > 0.f) ? mx / QMAX : 0.f;

    for (int i = tid; i < I_DIM / 4; i += blockDim.x) {
        float v[4];
        *(float4*)v = ((const float4*)xs)[i];
        uint32_t p1, p2;
        quant4_pack(v, s, p1, p2);
        ((uint32_t*)g_X1)[(size_t)m * (I_DIM / 4) + i] = p1;
        ((uint32_t*)g_X2)[(size_t)m * (I_DIM / 4) + i] = p2;
    }
}

// ---------------------------------------------------------------------------
// Kernel 3: int8 IMMA GEMM. Block 128x64, BK=64 bytes. 8 warps, warp 32x32.
// hi += X1*W1 ; lo += X1*W2 + X2*W1.  Round-1-proven 2-stage pipeline.
// ---------------------------------------------------------------------------
static constexpr int BM = 128, BN = 64, BK = 64;
static constexpr int KT = I_DIM / BK;          // 64
static constexpr int A_TILE = BM * 64;         // 8192
static constexpr int W_TILE = BN * 64;         // 4096
static constexpr int STAGE = 2 * A_TILE + 2 * W_TILE;   // 24576
static constexpr int SMEM_BYTES = 2 * STAGE;            // 49152
static constexpr int OFF_X1 = 0, OFF_X2 = A_TILE;
static constexpr int OFF_W1 = 2 * A_TILE, OFF_W2 = 2 * A_TILE + W_TILE;

__device__ __forceinline__ uint32_t cvta_smem(const void* p) {
    return (uint32_t)__cvta_generic_to_shared(p);
}
__device__ __forceinline__ void cp_async16(uint32_t s, const void* g) {
    asm volatile("cp.async.cg.shared.global [%0], [%1], 16;" :: "r"(s), "l"(g));
}
__device__ __forceinline__ void ldsm4(uint32_t (&r)[4], uint32_t addr) {
    asm volatile("ldmatrix.sync.aligned.m8n8.x4.shared.b16 {%0,%1,%2,%3}, [%4];"
                 : "=r"(r[0]), "=r"(r[1]), "=r"(r[2]), "=r"(r[3]) : "r"(addr));
}
__device__ __forceinline__ void imma(int (&d)[4], const uint32_t (&a)[4],
                                     uint32_t b0, uint32_t b1) {
    asm volatile(
        "mma.sync.aligned.m16n8k32.row.col.s32.s8.s8.s32 "
        "{%0,%1,%2,%3}, {%4,%5,%6,%7}, {%8,%9}, {%0,%1,%2,%3};"
        : "+r"(d[0]), "+r"(d[1]), "+r"(d[2]), "+r"(d[3])
        : "r"(a[0]), "r"(a[1]), "r"(a[2]), "r"(a[3]), "r"(b0), "r"(b1));
}
// conflict-free swizzle for 64B rows (validated in round 1)
__device__ __forceinline__ uint32_t swz(int row, int c) {
    return (uint32_t)(row * 64 + ((c ^ ((row >> 1) & 3)) << 4));
}

__global__ __launch_bounds__(256, 2)
void gemm_i8(const float* __restrict__ bias, float* __restrict__ out) {
    extern __shared__ __align__(16) uint8_t smem[];
    const uint32_t sbase = cvta_smem(smem);
    const int tid  = threadIdx.x;
    const int lane = tid & 31;
    const int warp = tid >> 5;
    const int wm = warp >> 1;   // 0..3
    const int wn = warp & 1;    // 0..1
    const int m0 = blockIdx.x * BM;
    const int n0 = blockIdx.y * BN;

    // Loader geometry (computed once)
    const int arow = tid >> 2, ac = tid & 3;           // rows 0..63 (+64 for A)
    const uint32_t aoff0 = swz(arow, ac);
    const uint32_t aoff1 = swz(arow + 64, ac);
    const size_t ag0 = (size_t)(m0 + arow) * I_DIM + ac * 16;
    const size_t ag1 = (size_t)(m0 + arow + 64) * I_DIM + ac * 16;
    const uint32_t woff = swz(arow, ac);               // W: rows 0..63
    const size_t wg0 = (size_t)(n0 + arow) * I_DIM + ac * 16;

    int hi[2][4][4], lo[2][4][4];
#pragma unroll
    for (int a = 0; a < 2; a++)
#pragma unroll
        for (int b = 0; b < 4; b++)
#pragma unroll
            for (int c = 0; c < 4; c++) { hi[a][b][c] = 0; lo[a][b][c] = 0; }

#define LOAD_STAGE(KK, STG) do {                                              \
        const uint32_t st = sbase + (STG) * STAGE;                            \
        cp_async16(st + OFF_X1 + aoff0, g_X1 + ag0 + (KK));                   \
        cp_async16(st + OFF_X1 + aoff1, g_X1 + ag1 + (KK));                   \
        cp_async16(st + OFF_X2 + aoff0, g_X2 + ag0 + (KK));                   \
        cp_async16(st + OFF_X2 + aoff1, g_X2 + ag1 + (KK));                   \
        cp_async16(st + OFF_W1 + woff,  g_W1 + wg0 + (KK));                   \
        cp_async16(st + OFF_W2 + woff,  g_W2 + wg0 + (KK));                   \
        asm volatile("cp.async.commit_group;" ::: "memory");                  \
    } while (0)

    LOAD_STAGE(0, 0);

    for (int kt = 0; kt < KT; kt++) {
        asm volatile("cp.async.wait_group 0;" ::: "memory");
        __syncthreads();
        if (kt + 1 < KT) LOAD_STAGE((kt + 1) * BK, (kt + 1) & 1);

        const uint32_t sb = sbase + (kt & 1) * STAGE;
#pragma unroll
        for (int ks = 0; ks < 2; ks++) {
            uint32_t a1[2][4], a2[2][4];
#pragma unroll
            for (int mt = 0; mt < 2; mt++) {
                const uint32_t off =
                    swz(wm * 32 + mt * 16 + (lane & 15), ks * 2 + (lane >> 4));
                ldsm4(a1[mt], sb + OFF_X1 + off);
                ldsm4(a2[mt], sb + OFF_X2 + off);
            }
#pragma unroll
            for (int nb = 0; nb < 2; nb++) {
                const uint32_t off =
                    swz(wn * 32 + nb * 16 + (lane & 7) + ((lane >> 4) << 3),
                        ks * 2 + ((lane >> 3) & 1));
                uint32_t w1[4], w2[4];
                ldsm4(w1, sb + OFF_W1 + off);
                ldsm4(w2, sb + OFF_W2 + off);
#pragma unroll
                for (int mt = 0; mt < 2; mt++) {
                    imma(hi[mt][nb * 2 + 0], a1[mt], w1[0], w1[1]);
                    imma(hi[mt][nb * 2 + 1], a1[mt], w1[2], w1[3]);
                    imma(lo[mt][nb * 2 + 0], a1[mt], w2[0], w2[1]);
                    imma(lo[mt][nb * 2 + 1], a1[mt], w2[2], w2[3]);
                    imma(lo[mt][nb * 2 + 0], a2[mt], w1[0], w1[1]);
                    imma(lo[mt][nb * 2 + 1], a2[mt], w1[2], w1[3]);
                }
            }
        }
        __syncthreads();
    }
#undef LOAD_STAGE

    // Epilogue: out = fx[m]*fw[o]*128*(128*hi + lo) + bias
#pragma unroll
    for (int mt = 0; mt < 2; mt++) {
        const int r0 = m0 + wm * 32 + mt * 16 + (lane >> 2);
        const float fxa = g_fx[r0];
        const float fxb = g_fx[r0 + 8];
#pragma unroll
        for (int q = 0; q < 4; q++) {
            const int col = n0 + wn * 32 + q * 8 + (lane & 3) * 2;
            const float2 fw2 = *(const float2*)(g_fw + col);
            const float2 bb  = *(const float2*)(bias + col);
            const float sA0 = fxa * fw2.x * 128.f, sA1 = fxa * fw2.y * 128.f;
            const float sB0 = fxb * fw2.x * 128.f, sB1 = fxb * fw2.y * 128.f;
            const float t0 = (float)((((long long)hi[mt][q][0]) << 7) + lo[mt][q][0]);
            const float t1 = (float)((((long long)hi[mt][q][1]) << 7) + lo[mt][q][1]);
            const float t2 = (float)((((long long)hi[mt][q][2]) << 7) + lo[mt][q][2]);
            const float t3 = (float)((((long long)hi[mt][q][3]) << 7) + lo[mt][q][3]);
            float2 v0 = {fmaf(t0, sA0, bb.x), fmaf(t1, sA1, bb.y)};
            float2 v1 = {fmaf(t2, sB0, bb.x), fmaf(t3, sB1, bb.y)};
            *(float2*)(out + (size_t)r0 * O_DIM + col) = v0;
            *(float2*)(out + (size_t)(r0 + 8) * O_DIM + col) = v1;
        }
    }
}

// ---------------------------------------------------------------------------
extern "C" void kernel_launch(void* const* d_in, const int* in_sizes, int n_in,
                              void* d_out, int out_size) {
    const int*   qweight   = (const int*)d_in[0];
    const float* scales    = (const float*)d_in[1];
    const float* lora_up   = (const float*)d_in[2];
    const float* lora_down = (const float*)d_in[3];
    const float* bias      = (const float*)d_in[4];
    const float* x         = (const float*)d_in[5];
    float* out = (float*)d_out;

    prep_w_kernel<<<O_DIM, 256>>>(qweight, scales, lora_up, lora_down);
    prep_x_kernel<<<M_DIM, 256>>>(x);

    cudaFuncSetAttribute(gemm_i8,
                         cudaFuncAttributeMaxDynamicSharedMemorySize, SMEM_BYTES);
    dim3 grid(M_DIM / BM, O_DIM / BN);   // (128, 64), M-fast
    gemm_i8<<<grid, 256, SMEM_BYTES>>>(bias, out);
}

// round 6
// speedup vs baseline: 7.5749x; 7.5749x over previous
#include <cuda_runtime.h>
#include <cuda_fp16.h>
#include <cstdint>

// Problem constants
static constexpr int O_DIM = 4096;     // out features (N)
static constexpr int I_DIM = 4096;     // in features (K)
static constexpr int M_DIM = 8 * 2048; // batch*seq (M)
static constexpr int R_DIM = 16;       // LoRA rank

// Scratch: fp16 operands (device globals — no allocation allowed)
__device__ __align__(16) __half g_Wq[(size_t)O_DIM * I_DIM];
__device__ __align__(16) __half g_Xq[(size_t)M_DIM * I_DIM];

// ---------------------------------------------------------------------------
// Kernel 1: W = scales*(q-128) + 0.5*up@down  -> fp16
// ---------------------------------------------------------------------------
__global__ void prep_w_kernel(const int* __restrict__ qw,
                              const float* __restrict__ scales,
                              const float* __restrict__ up,
                              const float* __restrict__ down) {
    const int o = blockIdx.x;
    const int tid = threadIdx.x;
    __shared__ float up_s[R_DIM];
    if (tid < R_DIM) up_s[tid] = up[o * R_DIM + tid];
    __syncthreads();

    const int4* qrow = (const int4*)(qw + (size_t)o * I_DIM);
    for (int i = tid; i < I_DIM / 4; i += blockDim.x) {
        const int4 q = qrow[i];
        const float sc = scales[o * (I_DIM / 32) + (i >> 3)];
        float l[4] = {0.f, 0.f, 0.f, 0.f};
#pragma unroll
        for (int r = 0; r < R_DIM; r++) {
            const float4 d4 = ((const float4*)(down + (size_t)r * I_DIM))[i];
            const float u = up_s[r];
            l[0] = fmaf(u, d4.x, l[0]); l[1] = fmaf(u, d4.y, l[1]);
            l[2] = fmaf(u, d4.z, l[2]); l[3] = fmaf(u, d4.w, l[3]);
        }
        float w[4];
        w[0] = fmaf(sc, (float)q.x - 128.f, 0.5f * l[0]);
        w[1] = fmaf(sc, (float)q.y - 128.f, 0.5f * l[1]);
        w[2] = fmaf(sc, (float)q.z - 128.f, 0.5f * l[2]);
        w[3] = fmaf(sc, (float)q.w - 128.f, 0.5f * l[3]);
        union { __half h[4]; uint2 u; } P;
#pragma unroll
        for (int j = 0; j < 4; j++) P.h[j] = __float2half_rn(w[j]);
        ((uint2*)g_Wq)[(size_t)o * (I_DIM / 4) + i] = P.u;
    }
}

// ---------------------------------------------------------------------------
// Kernel 2: x (fp32) -> fp16
// ---------------------------------------------------------------------------
__global__ void prep_x_kernel(const float* __restrict__ x) {
    const size_t idx = (size_t)blockIdx.x * blockDim.x + threadIdx.x;
    if (idx >= (size_t)M_DIM * I_DIM / 4) return;
    const float4 v = ((const float4*)x)[idx];
    union { __half h[4]; uint2 u; } P;
    P.h[0] = __float2half_rn(v.x);
    P.h[1] = __float2half_rn(v.y);
    P.h[2] = __float2half_rn(v.z);
    P.h[3] = __float2half_rn(v.w);
    ((uint2*)g_Xq)[idx] = P.u;
}

// ---------------------------------------------------------------------------
// Kernel 3: fp16 GEMM  out[M][N] = Xq @ Wq^T + bias
// Round-1-proven skeleton: 128x128x32 tile, 8 warps (32x64 warp tile),
// 2-stage cp.async pipeline, single fp16 MMA chain, fp32 accumulate.
// ---------------------------------------------------------------------------
static constexpr int BM = 128, BN = 128, BK = 32;
static constexpr int KT = I_DIM / BK;          // 128 K-tiles
static constexpr int TILE_BYTES = BM * 64;     // 8192 B per buffer (row = 64B)
static constexpr int STAGE_BYTES = 2 * TILE_BYTES;   // A, B
static constexpr int SMEM_BYTES = 2 * STAGE_BYTES;   // 32768

__device__ __forceinline__ uint32_t cvta_smem(const void* p) {
    return (uint32_t)__cvta_generic_to_shared(p);
}
__device__ __forceinline__ void cp_async16(uint32_t s, const void* g) {
    asm volatile("cp.async.cg.shared.global [%0], [%1], 16;" :: "r"(s), "l"(g));
}
__device__ __forceinline__ void ldsm4(uint32_t (&r)[4], uint32_t addr) {
    asm volatile("ldmatrix.sync.aligned.m8n8.x4.shared.b16 {%0,%1,%2,%3}, [%4];"
                 : "=r"(r[0]), "=r"(r[1]), "=r"(r[2]), "=r"(r[3]) : "r"(addr));
}
__device__ __forceinline__ void mma16816(float (&d)[4], const uint32_t (&a)[4],
                                         uint32_t b0, uint32_t b1) {
    asm volatile(
        "mma.sync.aligned.m16n8k16.row.col.f32.f16.f16.f32 "
        "{%0,%1,%2,%3}, {%4,%5,%6,%7}, {%8,%9}, {%0,%1,%2,%3};"
        : "+f"(d[0]), "+f"(d[1]), "+f"(d[2]), "+f"(d[3])
        : "r"(a[0]), "r"(a[1]), "r"(a[2]), "r"(a[3]), "r"(b0), "r"(b1));
}

// Swizzle: 16B chunk c (0..3) in 64B row -> physical chunk c ^ ((row>>1)&3).
// (validated in round 1)
__device__ __forceinline__ uint32_t swz(int row, int c) {
    return (uint32_t)(row * 64 + ((c ^ ((row >> 1) & 3)) << 4));
}

__global__ __launch_bounds__(256, 2)
void gemm_fp16(const float* __restrict__ bias, float* __restrict__ out) {
    extern __shared__ __align__(16) uint8_t smem[];
    const int tid  = threadIdx.x;
    const int lane = tid & 31;
    const int warp = tid >> 5;
    const int wm = warp >> 1;   // 0..3 (M)
    const int wn = warp & 1;    // 0..1 (N)
    const int m0 = blockIdx.y * BM;
    const int n0 = blockIdx.x * BN;

    const __half* aQ = g_Xq + (size_t)m0 * I_DIM;
    const __half* bQ = g_Wq + (size_t)n0 * I_DIM;

    const uint32_t sbase = cvta_smem(smem);

    // Loader geometry: 512 16B-chunks per buffer; thread covers rows r0 and r0+64.
    const int ldRow = tid >> 2;   // 0..63
    const int ldC   = tid & 3;
    const uint32_t so0 = swz(ldRow, ldC);
    const uint32_t so1 = swz(ldRow + 64, ldC);
    const size_t g0 = (size_t)ldRow * I_DIM + ldC * 8;
    const size_t g1 = (size_t)(ldRow + 64) * I_DIM + ldC * 8;

    float acc[2][8][4];
#pragma unroll
    for (int a = 0; a < 2; a++)
#pragma unroll
        for (int b = 0; b < 8; b++)
#pragma unroll
            for (int c = 0; c < 4; c++) acc[a][b][c] = 0.f;

#define LOAD_STAGE(K0, STG) do {                                              \
        const uint32_t sb = sbase + (STG) * STAGE_BYTES;                      \
        cp_async16(sb + 0 * TILE_BYTES + so0, aQ + g0 + (K0));                \
        cp_async16(sb + 0 * TILE_BYTES + so1, aQ + g1 + (K0));                \
        cp_async16(sb + 1 * TILE_BYTES + so0, bQ + g0 + (K0));                \
        cp_async16(sb + 1 * TILE_BYTES + so1, bQ + g1 + (K0));                \
        asm volatile("cp.async.commit_group;");                               \
    } while (0)

    LOAD_STAGE(0, 0);

    for (int kt = 0; kt < KT; kt++) {
        asm volatile("cp.async.wait_group 0;");
        __syncthreads();
        if (kt + 1 < KT) LOAD_STAGE((kt + 1) * BK, (kt + 1) & 1);

        const uint32_t sb  = sbase + (kt & 1) * STAGE_BYTES;
        const uint32_t aB = sb + 0 * TILE_BYTES;
        const uint32_t bB = sb + 1 * TILE_BYTES;

#pragma unroll
        for (int ks = 0; ks < 2; ks++) {
            uint32_t af[2][4];
#pragma unroll
            for (int mt = 0; mt < 2; mt++) {
                const int r = wm * 32 + mt * 16 + (lane & 15);
                const int c = ks * 2 + (lane >> 4);
                ldsm4(af[mt], aB + swz(r, c));
            }
#pragma unroll
            for (int np = 0; np < 4; np++) {
                const int r = wn * 64 + np * 16 + (lane & 7) + ((lane >> 4) << 3);
                const int c = ks * 2 + ((lane >> 3) & 1);
                uint32_t bf[4];
                ldsm4(bf, bB + swz(r, c));
#pragma unroll
                for (int mt = 0; mt < 2; mt++) {
                    mma16816(acc[mt][np * 2 + 0], af[mt], bf[0], bf[1]);
                    mma16816(acc[mt][np * 2 + 1], af[mt], bf[2], bf[3]);
                }
            }
        }
        __syncthreads();
    }
#undef LOAD_STAGE

    // Epilogue: + bias, fp32 out, float2 stores
#pragma unroll
    for (int mt = 0; mt < 2; mt++) {
#pragma unroll
        for (int nt = 0; nt < 8; nt++) {
            const int row = m0 + wm * 32 + mt * 16 + (lane >> 2);
            const int col = n0 + wn * 64 + nt * 8 + (lane & 3) * 2;
            const float b0 = bias[col], b1 = bias[col + 1];
            float2 v0 = {acc[mt][nt][0] + b0, acc[mt][nt][1] + b1};
            float2 v1 = {acc[mt][nt][2] + b0, acc[mt][nt][3] + b1};
            *(float2*)(out + (size_t)row * O_DIM + col) = v0;
            *(float2*)(out + (size_t)(row + 8) * O_DIM + col) = v1;
        }
    }
}

// ---------------------------------------------------------------------------
extern "C" void kernel_launch(void* const* d_in, const int* in_sizes, int n_in,
                              void* d_out, int out_size) {
    const int*   qweight   = (const int*)d_in[0];
    const float* scales    = (const float*)d_in[1];
    const float* lora_up   = (const float*)d_in[2];
    const float* lora_down = (const float*)d_in[3];
    const float* bias      = (const float*)d_in[4];
    const float* x         = (const float*)d_in[5];
    float* out = (float*)d_out;

    prep_w_kernel<<<O_DIM, 256>>>(qweight, scales, lora_up, lora_down);

    const size_t n4 = (size_t)M_DIM * I_DIM / 4;
    prep_x_kernel<<<(unsigned)((n4 + 255) / 256), 256>>>(x);

    cudaFuncSetAttribute(gemm_fp16,
                         cudaFuncAttributeMaxDynamicSharedMemorySize, SMEM_BYTES);
    dim3 grid(O_DIM / BN, M_DIM / BM);  // (32, 128)
    gemm_fp16<<<grid, 256, SMEM_BYTES>>>(bias, out);
}

// round 7
// speedup vs baseline: 7.8749x; 1.0396x over previous
#include <cuda_runtime.h>
#include <cuda_fp16.h>
#include <cstdint>

// Problem constants
static constexpr int O_DIM = 4096;     // out features (N)
static constexpr int I_DIM = 4096;     // in features (K)
static constexpr int M_DIM = 8 * 2048; // batch*seq (M)
static constexpr int R_DIM = 16;       // LoRA rank

// Scratch: fp16 operands (device globals — no allocation allowed)
__device__ __align__(16) __half g_Wq[(size_t)O_DIM * I_DIM];
__device__ __align__(16) __half g_Xq[(size_t)M_DIM * I_DIM];

// ---------------------------------------------------------------------------
// Kernel 1: W = scales*(q-128) + 0.5*up@down  -> fp16
// ---------------------------------------------------------------------------
__global__ void prep_w_kernel(const int* __restrict__ qw,
                              const float* __restrict__ scales,
                              const float* __restrict__ up,
                              const float* __restrict__ down) {
    const int o = blockIdx.x;
    const int tid = threadIdx.x;
    __shared__ float up_s[R_DIM];
    if (tid < R_DIM) up_s[tid] = up[o * R_DIM + tid];
    __syncthreads();

    const int4* qrow = (const int4*)(qw + (size_t)o * I_DIM);
    for (int i = tid; i < I_DIM / 4; i += blockDim.x) {
        const int4 q = qrow[i];
        const float sc = scales[o * (I_DIM / 32) + (i >> 3)];
        float l[4] = {0.f, 0.f, 0.f, 0.f};
#pragma unroll
        for (int r = 0; r < R_DIM; r++) {
            const float4 d4 = ((const float4*)(down + (size_t)r * I_DIM))[i];
            const float u = up_s[r];
            l[0] = fmaf(u, d4.x, l[0]); l[1] = fmaf(u, d4.y, l[1]);
            l[2] = fmaf(u, d4.z, l[2]); l[3] = fmaf(u, d4.w, l[3]);
        }
        float w[4];
        w[0] = fmaf(sc, (float)q.x - 128.f, 0.5f * l[0]);
        w[1] = fmaf(sc, (float)q.y - 128.f, 0.5f * l[1]);
        w[2] = fmaf(sc, (float)q.z - 128.f, 0.5f * l[2]);
        w[3] = fmaf(sc, (float)q.w - 128.f, 0.5f * l[3]);
        union { __half h[4]; uint2 u; } P;
#pragma unroll
        for (int j = 0; j < 4; j++) P.h[j] = __float2half_rn(w[j]);
        ((uint2*)g_Wq)[(size_t)o * (I_DIM / 4) + i] = P.u;
    }
}

// ---------------------------------------------------------------------------
// Kernel 2: x (fp32) -> fp16
// ---------------------------------------------------------------------------
__global__ void prep_x_kernel(const float* __restrict__ x) {
    const size_t idx = (size_t)blockIdx.x * blockDim.x + threadIdx.x;
    if (idx >= (size_t)M_DIM * I_DIM / 4) return;
    const float4 v = ((const float4*)x)[idx];
    union { __half h[4]; uint2 u; } P;
    P.h[0] = __float2half_rn(v.x);
    P.h[1] = __float2half_rn(v.y);
    P.h[2] = __float2half_rn(v.z);
    P.h[3] = __float2half_rn(v.w);
    ((uint2*)g_Xq)[idx] = P.u;
}

// ---------------------------------------------------------------------------
// Kernel 3: fp16 GEMM  out[M][N] = Xq @ Wq^T + bias
// 128x128x32 tile, 8 warps (32x64 warp tile), 4-stage cp.async pipeline
// (wait_group 2, one barrier per K-tile), fp32 accumulate.
// ---------------------------------------------------------------------------
static constexpr int BM = 128, BN = 128, BK = 32;
static constexpr int KT = I_DIM / BK;          // 128 K-tiles
static constexpr int NS = 4;                   // pipeline stages
static constexpr int TILE_BYTES = BM * 64;     // 8192 B per buffer (row = 64B)
static constexpr int STAGE_BYTES = 2 * TILE_BYTES;   // A, B
static constexpr int SMEM_BYTES = NS * STAGE_BYTES;  // 65536

__device__ __forceinline__ uint32_t cvta_smem(const void* p) {
    return (uint32_t)__cvta_generic_to_shared(p);
}
__device__ __forceinline__ void cp_async16(uint32_t s, const void* g) {
    asm volatile("cp.async.cg.shared.global [%0], [%1], 16;" :: "r"(s), "l"(g));
}
__device__ __forceinline__ void ldsm4(uint32_t (&r)[4], uint32_t addr) {
    asm volatile("ldmatrix.sync.aligned.m8n8.x4.shared.b16 {%0,%1,%2,%3}, [%4];"
                 : "=r"(r[0]), "=r"(r[1]), "=r"(r[2]), "=r"(r[3]) : "r"(addr));
}
__device__ __forceinline__ void mma16816(float (&d)[4], const uint32_t (&a)[4],
                                         uint32_t b0, uint32_t b1) {
    asm volatile(
        "mma.sync.aligned.m16n8k16.row.col.f32.f16.f16.f32 "
        "{%0,%1,%2,%3}, {%4,%5,%6,%7}, {%8,%9}, {%0,%1,%2,%3};"
        : "+f"(d[0]), "+f"(d[1]), "+f"(d[2]), "+f"(d[3])
        : "r"(a[0]), "r"(a[1]), "r"(a[2]), "r"(a[3]), "r"(b0), "r"(b1));
}

// Swizzle: 16B chunk c (0..3) in 64B row -> physical chunk c ^ ((row>>1)&3).
__device__ __forceinline__ uint32_t swz(int row, int c) {
    return (uint32_t)(row * 64 + ((c ^ ((row >> 1) & 3)) << 4));
}

__global__ __launch_bounds__(256, 2)
void gemm_fp16(const float* __restrict__ bias, float* __restrict__ out) {
    extern __shared__ __align__(16) uint8_t smem[];
    const int tid  = threadIdx.x;
    const int lane = tid & 31;
    const int warp = tid >> 5;
    const int wm = warp >> 1;   // 0..3 (M)
    const int wn = warp & 1;    // 0..1 (N)
    const int m0 = blockIdx.y * BM;
    const int n0 = blockIdx.x * BN;

    const __half* aQ = g_Xq + (size_t)m0 * I_DIM;
    const __half* bQ = g_Wq + (size_t)n0 * I_DIM;

    const uint32_t sbase = cvta_smem(smem);

    // Loader geometry: 512 16B-chunks per buffer; thread covers rows r0 and r0+64.
    const int ldRow = tid >> 2;   // 0..63
    const int ldC   = tid & 3;
    const uint32_t so0 = swz(ldRow, ldC);
    const uint32_t so1 = swz(ldRow + 64, ldC);
    const size_t g0 = (size_t)ldRow * I_DIM + ldC * 8;
    const size_t g1 = (size_t)(ldRow + 64) * I_DIM + ldC * 8;

    // Loop-invariant ldsm offsets
    uint32_t aoff[2][2], boff[2][4];
#pragma unroll
    for (int ks = 0; ks < 2; ks++) {
#pragma unroll
        for (int mt = 0; mt < 2; mt++)
            aoff[ks][mt] = swz(wm * 32 + mt * 16 + (lane & 15),
                               ks * 2 + (lane >> 4));
#pragma unroll
        for (int np = 0; np < 4; np++)
            boff[ks][np] = swz(wn * 64 + np * 16 + (lane & 7) + ((lane >> 4) << 3),
                               ks * 2 + ((lane >> 3) & 1));
    }

    float acc[2][8][4];
#pragma unroll
    for (int a = 0; a < 2; a++)
#pragma unroll
        for (int b = 0; b < 8; b++)
#pragma unroll
            for (int c = 0; c < 4; c++) acc[a][b][c] = 0.f;

#define LOAD_STAGE(T) do {                                                    \
        const uint32_t sb = sbase + ((T) & (NS - 1)) * STAGE_BYTES;           \
        const size_t k0 = (size_t)(T) * BK;                                   \
        cp_async16(sb + 0 * TILE_BYTES + so0, aQ + g0 + k0);                  \
        cp_async16(sb + 0 * TILE_BYTES + so1, aQ + g1 + k0);                  \
        cp_async16(sb + 1 * TILE_BYTES + so0, bQ + g0 + k0);                  \
        cp_async16(sb + 1 * TILE_BYTES + so1, bQ + g1 + k0);                  \
        asm volatile("cp.async.commit_group;");                               \
    } while (0)

    // Prologue: stages 0..NS-2
#pragma unroll
    for (int t = 0; t < NS - 1; t++) LOAD_STAGE(t);

    for (int kt = 0; kt < KT; kt++) {
        asm volatile("cp.async.wait_group %0;" :: "n"(NS - 2));
        __syncthreads();   // stage kt ready; all warps done with stage kt-1
        if (kt + NS - 1 < KT) {
            LOAD_STAGE(kt + NS - 1);
        } else {
            asm volatile("cp.async.commit_group;");  // empty group keeps count
        }

        const uint32_t sb = sbase + (kt & (NS - 1)) * STAGE_BYTES;
        const uint32_t aB = sb + 0 * TILE_BYTES;
        const uint32_t bB = sb + 1 * TILE_BYTES;

#pragma unroll
        for (int ks = 0; ks < 2; ks++) {
            uint32_t af[2][4];
#pragma unroll
            for (int mt = 0; mt < 2; mt++) ldsm4(af[mt], aB + aoff[ks][mt]);
#pragma unroll
            for (int np = 0; np < 4; np++) {
                uint32_t bf[4];
                ldsm4(bf, bB + boff[ks][np]);
#pragma unroll
                for (int mt = 0; mt < 2; mt++) {
                    mma16816(acc[mt][np * 2 + 0], af[mt], bf[0], bf[1]);
                    mma16816(acc[mt][np * 2 + 1], af[mt], bf[2], bf[3]);
                }
            }
        }
    }
#undef LOAD_STAGE

    // Epilogue: + bias, fp32 out, float2 stores
#pragma unroll
    for (int mt = 0; mt < 2; mt++) {
#pragma unroll
        for (int nt = 0; nt < 8; nt++) {
            const int row = m0 + wm * 32 + mt * 16 + (lane >> 2);
            const int col = n0 + wn * 64 + nt * 8 + (lane & 3) * 2;
            const float b0 = bias[col], b1 = bias[col + 1];
            float2 v0 = {acc[mt][nt][0] + b0, acc[mt][nt][1] + b1};
            float2 v1 = {acc[mt][nt][2] + b0, acc[mt][nt][3] + b1};
            *(float2*)(out + (size_t)row * O_DIM + col) = v0;
            *(float2*)(out + (size_t)(row + 8) * O_DIM + col) = v1;
        }
    }
}

// ---------------------------------------------------------------------------
extern "C" void kernel_launch(void* const* d_in, const int* in_sizes, int n_in,
                              void* d_out, int out_size) {
    const int*   qweight   = (const int*)d_in[0];
    const float* scales    = (const float*)d_in[1];
    const float* lora_up   = (const float*)d_in[2];
    const float* lora_down = (const float*)d_in[3];
    const float* bias      = (const float*)d_in[4];
    const float* x         = (const float*)d_in[5];
    float* out = (float*)d_out;

    prep_w_kernel<<<O_DIM, 256>>>(qweight, scales, lora_up, lora_down);

    const size_t n4 = (size_t)M_DIM * I_DIM / 4;
    prep_x_kernel<<<(unsigned)((n4 + 255) / 256), 256>>>(x);

    cudaFuncSetAttribute(gemm_fp16,
                         cudaFuncAttributeMaxDynamicSharedMemorySize, SMEM_BYTES);
    dim3 grid(O_DIM / BN, M_DIM / BM);  // (32, 128)
    gemm_fp16<<<grid, 256, SMEM_BYTES>>>(bias, out);
}

// round 8
// speedup vs baseline: 7.9119x; 1.0047x over previous
#include <cuda_runtime.h>
#include <cuda_fp16.h>
#include <cstdint>

// Problem constants
static constexpr int O_DIM = 4096;     // out features (N)
static constexpr int I_DIM = 4096;     // in features (K)
static constexpr int M_DIM = 8 * 2048; // batch*seq (M)
static constexpr int R_DIM = 16;       // LoRA rank

// Scratch: fp16 operands (device globals — no allocation allowed)
__device__ __align__(16) __half g_Wq[(size_t)O_DIM * I_DIM];
__device__ __align__(16) __half g_Xq[(size_t)M_DIM * I_DIM];

// ---------------------------------------------------------------------------
// Fused prep kernel.
//   blocks [0, O_DIM):            W rows -> fp16 (compute-heavy)
//   blocks [O_DIM, O_DIM+XBLK):   x fp32 -> fp16, 2 float4 per thread (BW-heavy)
// Co-residency overlaps the FMA-bound W path with the bandwidth-bound X path.
// ---------------------------------------------------------------------------
static constexpr int XPT = 2;  // float4 elements per thread in x path
static constexpr int XBLK =
    (int)(((size_t)M_DIM * I_DIM / 4) / (256 * XPT));   // 32768 blocks

__global__ void prep_fused(const int* __restrict__ qw,
                           const float* __restrict__ scales,
                           const float* __restrict__ up,
                           const float* __restrict__ down,
                           const float* __restrict__ x) {
    const int tid = threadIdx.x;
    if (blockIdx.x < O_DIM) {
        // ---- W path ----
        const int o = blockIdx.x;
        __shared__ float up_s[R_DIM];
        if (tid < R_DIM) up_s[tid] = up[o * R_DIM + tid];
        __syncthreads();

        const int4* qrow = (const int4*)(qw + (size_t)o * I_DIM);
        for (int i = tid; i < I_DIM / 4; i += blockDim.x) {
            const int4 q = qrow[i];
            const float sc = scales[o * (I_DIM / 32) + (i >> 3)];
            float l[4] = {0.f, 0.f, 0.f, 0.f};
#pragma unroll
            for (int r = 0; r < R_DIM; r++) {
                const float4 d4 = ((const float4*)(down + (size_t)r * I_DIM))[i];
                const float u = up_s[r];
                l[0] = fmaf(u, d4.x, l[0]); l[1] = fmaf(u, d4.y, l[1]);
                l[2] = fmaf(u, d4.z, l[2]); l[3] = fmaf(u, d4.w, l[3]);
            }
            float w[4];
            w[0] = fmaf(sc, (float)q.x - 128.f, 0.5f * l[0]);
            w[1] = fmaf(sc, (float)q.y - 128.f, 0.5f * l[1]);
            w[2] = fmaf(sc, (float)q.z - 128.f, 0.5f * l[2]);
            w[3] = fmaf(sc, (float)q.w - 128.f, 0.5f * l[3]);
            union { __half h[4]; uint2 u; } P;
#pragma unroll
            for (int j = 0; j < 4; j++) P.h[j] = __float2half_rn(w[j]);
            ((uint2*)g_Wq)[(size_t)o * (I_DIM / 4) + i] = P.u;
        }
    } else {
        // ---- X path: 2 consecutive float4 -> one uint4 streaming store ----
        const size_t t = (size_t)(blockIdx.x - O_DIM) * blockDim.x + tid;
        const size_t i4 = t * XPT;               // first float4 index
        const float4 v0 = ((const float4*)x)[i4];
        const float4 v1 = ((const float4*)x)[i4 + 1];
        union { __half h[8]; uint4 u; } P;
        P.h[0] = __float2half_rn(v0.x); P.h[1] = __float2half_rn(v0.y);
        P.h[2] = __float2half_rn(v0.z); P.h[3] = __float2half_rn(v0.w);
        P.h[4] = __float2half_rn(v1.x); P.h[5] = __float2half_rn(v1.y);
        P.h[6] = __float2half_rn(v1.z); P.h[7] = __float2half_rn(v1.w);
        __stcs((uint4*)g_Xq + t, P.u);
    }
}

// ---------------------------------------------------------------------------
// GEMM  out[M][N] = Xq @ Wq^T + bias
// 128x128x32 tile, 8 warps (32x64 warp tile), 4-stage cp.async pipeline
// (wait_group 2, one barrier per K-tile), fp32 accumulate. (proven)
// ---------------------------------------------------------------------------
static constexpr int BM = 128, BN = 128, BK = 32;
static constexpr int KT = I_DIM / BK;          // 128 K-tiles
static constexpr int NS = 4;                   // pipeline stages
static constexpr int TILE_BYTES = BM * 64;     // 8192 B per buffer (row = 64B)
static constexpr int STAGE_BYTES = 2 * TILE_BYTES;   // A, B
static constexpr int SMEM_BYTES = NS * STAGE_BYTES;  // 65536

__device__ __forceinline__ uint32_t cvta_smem(const void* p) {
    return (uint32_t)__cvta_generic_to_shared(p);
}
__device__ __forceinline__ void cp_async16(uint32_t s, const void* g) {
    asm volatile("cp.async.cg.shared.global [%0], [%1], 16;" :: "r"(s), "l"(g));
}
__device__ __forceinline__ void ldsm4(uint32_t (&r)[4], uint32_t addr) {
    asm volatile("ldmatrix.sync.aligned.m8n8.x4.shared.b16 {%0,%1,%2,%3}, [%4];"
                 : "=r"(r[0]), "=r"(r[1]), "=r"(r[2]), "=r"(r[3]) : "r"(addr));
}
__device__ __forceinline__ void mma16816(float (&d)[4], const uint32_t (&a)[4],
                                         uint32_t b0, uint32_t b1) {
    asm volatile(
        "mma.sync.aligned.m16n8k16.row.col.f32.f16.f16.f32 "
        "{%0,%1,%2,%3}, {%4,%5,%6,%7}, {%8,%9}, {%0,%1,%2,%3};"
        : "+f"(d[0]), "+f"(d[1]), "+f"(d[2]), "+f"(d[3])
        : "r"(a[0]), "r"(a[1]), "r"(a[2]), "r"(a[3]), "r"(b0), "r"(b1));
}

// Swizzle: 16B chunk c (0..3) in 64B row -> physical chunk c ^ ((row>>1)&3).
__device__ __forceinline__ uint32_t swz(int row, int c) {
    return (uint32_t)(row * 64 + ((c ^ ((row >> 1) & 3)) << 4));
}

__global__ __launch_bounds__(256, 2)
void gemm_fp16(const float* __restrict__ bias, float* __restrict__ out) {
    extern __shared__ __align__(16) uint8_t smem[];
    const int tid  = threadIdx.x;
    const int lane = tid & 31;
    const int warp = tid >> 5;
    const int wm = warp >> 1;   // 0..3 (M)
    const int wn = warp & 1;    // 0..1 (N)
    const int m0 = blockIdx.y * BM;
    const int n0 = blockIdx.x * BN;

    const __half* aQ = g_Xq + (size_t)m0 * I_DIM;
    const __half* bQ = g_Wq + (size_t)n0 * I_DIM;

    const uint32_t sbase = cvta_smem(smem);

    // Loader geometry: 512 16B-chunks per buffer; thread covers rows r0 and r0+64.
    const int ldRow = tid >> 2;   // 0..63
    const int ldC   = tid & 3;
    const uint32_t so0 = swz(ldRow, ldC);
    const uint32_t so1 = swz(ldRow + 64, ldC);
    const size_t g0 = (size_t)ldRow * I_DIM + ldC * 8;
    const size_t g1 = (size_t)(ldRow + 64) * I_DIM + ldC * 8;

    // Loop-invariant ldsm offsets
    uint32_t aoff[2][2], boff[2][4];
#pragma unroll
    for (int ks = 0; ks < 2; ks++) {
#pragma unroll
        for (int mt = 0; mt < 2; mt++)
            aoff[ks][mt] = swz(wm * 32 + mt * 16 + (lane & 15),
                               ks * 2 + (lane >> 4));
#pragma unroll
        for (int np = 0; np < 4; np++)
            boff[ks][np] = swz(wn * 64 + np * 16 + (lane & 7) + ((lane >> 4) << 3),
                               ks * 2 + ((lane >> 3) & 1));
    }

    float acc[2][8][4];
#pragma unroll
    for (int a = 0; a < 2; a++)
#pragma unroll
        for (int b = 0; b < 8; b++)
#pragma unroll
            for (int c = 0; c < 4; c++) acc[a][b][c] = 0.f;

#define LOAD_STAGE(T) do {                                                    \
        const uint32_t sb = sbase + ((T) & (NS - 1)) * STAGE_BYTES;           \
        const size_t k0 = (size_t)(T) * BK;                                   \
        cp_async16(sb + 0 * TILE_BYTES + so0, aQ + g0 + k0);                  \
        cp_async16(sb + 0 * TILE_BYTES + so1, aQ + g1 + k0);                  \
        cp_async16(sb + 1 * TILE_BYTES + so0, bQ + g0 + k0);                  \
        cp_async16(sb + 1 * TILE_BYTES + so1, bQ + g1 + k0);                  \
        asm volatile("cp.async.commit_group;");                               \
    } while (0)

    // Prologue: stages 0..NS-2
#pragma unroll
    for (int t = 0; t < NS - 1; t++) LOAD_STAGE(t);

    for (int kt = 0; kt < KT; kt++) {
        asm volatile("cp.async.wait_group %0;" :: "n"(NS - 2));
        __syncthreads();   // stage kt ready; all warps done with stage kt-1
        if (kt + NS - 1 < KT) {
            LOAD_STAGE(kt + NS - 1);
        } else {
            asm volatile("cp.async.commit_group;");  // empty group keeps count
        }

        const uint32_t sb = sbase + (kt & (NS - 1)) * STAGE_BYTES;
        const uint32_t aB = sb + 0 * TILE_BYTES;
        const uint32_t bB = sb + 1 * TILE_BYTES;

#pragma unroll
        for (int ks = 0; ks < 2; ks++) {
            uint32_t af[2][4];
#pragma unroll
            for (int mt = 0; mt < 2; mt++) ldsm4(af[mt], aB + aoff[ks][mt]);
#pragma unroll
            for (int np = 0; np < 4; np++) {
                uint32_t bf[4];
                ldsm4(bf, bB + boff[ks][np]);
#pragma unroll
                for (int mt = 0; mt < 2; mt++) {
                    mma16816(acc[mt][np * 2 + 0], af[mt], bf[0], bf[1]);
                    mma16816(acc[mt][np * 2 + 1], af[mt], bf[2], bf[3]);
                }
            }
        }
    }
#undef LOAD_STAGE

    // Epilogue: + bias, fp32 out, streaming float2 stores (write-once data)
#pragma unroll
    for (int mt = 0; mt < 2; mt++) {
#pragma unroll
        for (int nt = 0; nt < 8; nt++) {
            const int row = m0 + wm * 32 + mt * 16 + (lane >> 2);
            const int col = n0 + wn * 64 + nt * 8 + (lane & 3) * 2;
            const float b0 = bias[col], b1 = bias[col + 1];
            float2 v0 = {acc[mt][nt][0] + b0, acc[mt][nt][1] + b1};
            float2 v1 = {acc[mt][nt][2] + b0, acc[mt][nt][3] + b1};
            __stcs((float2*)(out + (size_t)row * O_DIM + col), v0);
            __stcs((float2*)(out + (size_t)(row + 8) * O_DIM + col), v1);
        }
    }
}

// ---------------------------------------------------------------------------
extern "C" void kernel_launch(void* const* d_in, const int* in_sizes, int n_in,
                              void* d_out, int out_size) {
    const int*   qweight   = (const int*)d_in[0];
    const float* scales    = (const float*)d_in[1];
    const float* lora_up   = (const float*)d_in[2];
    const float* lora_down = (const float*)d_in[3];
    const float* bias      = (const float*)d_in[4];
    const float* x         = (const float*)d_in[5];
    float* out = (float*)d_out;

    prep_fused<<<O_DIM + XBLK, 256>>>(qweight, scales, lora_up, lora_down, x);

    cudaFuncSetAttribute(gemm_fp16,
                         cudaFuncAttributeMaxDynamicSharedMemorySize, SMEM_BYTES);
    dim3 grid(O_DIM / BN, M_DIM / BM);  // (32, 128)
    gemm_fp16<<<grid, 256, SMEM_BYTES>>>(bias, out);
}

// round 9
// speedup vs baseline: 9.0509x; 1.1440x over previous
#include <cuda_runtime.h>
#include <cuda_fp16.h>
#include <cstdint>

// Problem constants
static constexpr int O_DIM = 4096;     // out features (N)
static constexpr int I_DIM = 4096;     // in features (K)
static constexpr int M_DIM = 8 * 2048; // batch*seq (M)
static constexpr int R_DIM = 16;       // LoRA rank

// Scratch: fp16 operands (device globals — no allocation allowed)
__device__ __align__(16) __half g_Wq[(size_t)O_DIM * I_DIM];
__device__ __align__(16) __half g_Xq[(size_t)M_DIM * I_DIM];

// ---------------------------------------------------------------------------
// Fused prep kernel (round-8, kept).
// ---------------------------------------------------------------------------
static constexpr int XPT = 2;  // float4 elements per thread in x path
static constexpr int XBLK =
    (int)(((size_t)M_DIM * I_DIM / 4) / (256 * XPT));   // 32768 blocks

__global__ void prep_fused(const int* __restrict__ qw,
                           const float* __restrict__ scales,
                           const float* __restrict__ up,
                           const float* __restrict__ down,
                           const float* __restrict__ x) {
    const int tid = threadIdx.x;
    if (blockIdx.x < O_DIM) {
        const int o = blockIdx.x;
        __shared__ float up_s[R_DIM];
        if (tid < R_DIM) up_s[tid] = up[o * R_DIM + tid];
        __syncthreads();

        const int4* qrow = (const int4*)(qw + (size_t)o * I_DIM);
        for (int i = tid; i < I_DIM / 4; i += blockDim.x) {
            const int4 q = qrow[i];
            const float sc = scales[o * (I_DIM / 32) + (i >> 3)];
            float l[4] = {0.f, 0.f, 0.f, 0.f};
#pragma unroll
            for (int r = 0; r < R_DIM; r++) {
                const float4 d4 = ((const float4*)(down + (size_t)r * I_DIM))[i];
                const float u = up_s[r];
                l[0] = fmaf(u, d4.x, l[0]); l[1] = fmaf(u, d4.y, l[1]);
                l[2] = fmaf(u, d4.z, l[2]); l[3] = fmaf(u, d4.w, l[3]);
            }
            float w[4];
            w[0] = fmaf(sc, (float)q.x - 128.f, 0.5f * l[0]);
            w[1] = fmaf(sc, (float)q.y - 128.f, 0.5f * l[1]);
            w[2] = fmaf(sc, (float)q.z - 128.f, 0.5f * l[2]);
            w[3] = fmaf(sc, (float)q.w - 128.f, 0.5f * l[3]);
            union { __half h[4]; uint2 u; } P;
#pragma unroll
            for (int j = 0; j < 4; j++) P.h[j] = __float2half_rn(w[j]);
            ((uint2*)g_Wq)[(size_t)o * (I_DIM / 4) + i] = P.u;
        }
    } else {
        const size_t t = (size_t)(blockIdx.x - O_DIM) * blockDim.x + tid;
        const size_t i4 = t * XPT;
        const float4 v0 = ((const float4*)x)[i4];
        const float4 v1 = ((const float4*)x)[i4 + 1];
        union { __half h[8]; uint4 u; } P;
        P.h[0] = __float2half_rn(v0.x); P.h[1] = __float2half_rn(v0.y);
        P.h[2] = __float2half_rn(v0.z); P.h[3] = __float2half_rn(v0.w);
        P.h[4] = __float2half_rn(v1.x); P.h[5] = __float2half_rn(v1.y);
        P.h[6] = __float2half_rn(v1.z); P.h[7] = __float2half_rn(v1.w);
        __stcs((uint4*)g_Xq + t, P.u);
    }
}

// ---------------------------------------------------------------------------
// GEMM  out[M][N] = Xq @ Wq^T + bias
// 128x128x32 block tile, 4 warps, warp tile 64x64 (halves ldsm per MMA),
// 4-stage cp.async pipeline (wait_group 2, one barrier per K-tile).
// ---------------------------------------------------------------------------
static constexpr int BM = 128, BN = 128, BK = 32;
static constexpr int KT = I_DIM / BK;          // 128 K-tiles
static constexpr int NS = 4;                   // pipeline stages
static constexpr int TILE_BYTES = BM * 64;     // 8192 B per buffer (row = 64B)
static constexpr int STAGE_BYTES = 2 * TILE_BYTES;   // A, B
static constexpr int SMEM_BYTES = NS * STAGE_BYTES;  // 65536
static constexpr int NTHREADS = 128;

__device__ __forceinline__ uint32_t cvta_smem(const void* p) {
    return (uint32_t)__cvta_generic_to_shared(p);
}
__device__ __forceinline__ void cp_async16(uint32_t s, const void* g) {
    asm volatile("cp.async.cg.shared.global [%0], [%1], 16;" :: "r"(s), "l"(g));
}
__device__ __forceinline__ void ldsm4(uint32_t (&r)[4], uint32_t addr) {
    asm volatile("ldmatrix.sync.aligned.m8n8.x4.shared.b16 {%0,%1,%2,%3}, [%4];"
                 : "=r"(r[0]), "=r"(r[1]), "=r"(r[2]), "=r"(r[3]) : "r"(addr));
}
__device__ __forceinline__ void mma16816(float (&d)[4], const uint32_t (&a)[4],
                                         uint32_t b0, uint32_t b1) {
    asm volatile(
        "mma.sync.aligned.m16n8k16.row.col.f32.f16.f16.f32 "
        "{%0,%1,%2,%3}, {%4,%5,%6,%7}, {%8,%9}, {%0,%1,%2,%3};"
        : "+f"(d[0]), "+f"(d[1]), "+f"(d[2]), "+f"(d[3])
        : "r"(a[0]), "r"(a[1]), "r"(a[2]), "r"(a[3]), "r"(b0), "r"(b1));
}

// Swizzle: 16B chunk c (0..3) in 64B row -> physical chunk c ^ ((row>>1)&3).
__device__ __forceinline__ uint32_t swz(int row, int c) {
    return (uint32_t)(row * 64 + ((c ^ ((row >> 1) & 3)) << 4));
}

__global__ __launch_bounds__(NTHREADS, 2)
void gemm_fp16(const float* __restrict__ bias, float* __restrict__ out) {
    extern __shared__ __align__(16) uint8_t smem[];
    const int tid  = threadIdx.x;
    const int lane = tid & 31;
    const int warp = tid >> 5;
    const int wm = warp >> 1;   // 0..1 (M)
    const int wn = warp & 1;    // 0..1 (N)
    const int m0 = blockIdx.y * BM;
    const int n0 = blockIdx.x * BN;

    const __half* aQ = g_Xq + (size_t)m0 * I_DIM;
    const __half* bQ = g_Wq + (size_t)n0 * I_DIM;

    const uint32_t sbase = cvta_smem(smem);

    // Loader geometry: 512 16B-chunks per buffer / 128 threads = 4 rows each.
    const int ldRow = tid >> 2;   // 0..31
    const int ldC   = tid & 3;
    uint32_t so[4];
    size_t gofs[4];
#pragma unroll
    for (int j = 0; j < 4; j++) {
        so[j] = swz(ldRow + 32 * j, ldC);
        gofs[j] = (size_t)(ldRow + 32 * j) * I_DIM + ldC * 8;
    }

    // Loop-invariant ldsm offsets (warp tile 64x64)
    uint32_t aoff[2][4], boff[2][4];
#pragma unroll
    for (int ks = 0; ks < 2; ks++) {
#pragma unroll
        for (int mt = 0; mt < 4; mt++)
            aoff[ks][mt] = swz(wm * 64 + mt * 16 + (lane & 15),
                               ks * 2 + (lane >> 4));
#pragma unroll
        for (int np = 0; np < 4; np++)
            boff[ks][np] = swz(wn * 64 + np * 16 + (lane & 7) + ((lane >> 4) << 3),
                               ks * 2 + ((lane >> 3) & 1));
    }

    float acc[4][8][4];
#pragma unroll
    for (int a = 0; a < 4; a++)
#pragma unroll
        for (int b = 0; b < 8; b++)
#pragma unroll
            for (int c = 0; c < 4; c++) acc[a][b][c] = 0.f;

#define LOAD_STAGE(T) do {                                                    \
        const uint32_t sb = sbase + ((T) & (NS - 1)) * STAGE_BYTES;           \
        const size_t k0 = (size_t)(T) * BK;                                   \
        _Pragma("unroll")                                                     \
        for (int j = 0; j < 4; j++) {                                         \
            cp_async16(sb + 0 * TILE_BYTES + so[j], aQ + gofs[j] + k0);       \
            cp_async16(sb + 1 * TILE_BYTES + so[j], bQ + gofs[j] + k0);       \
        }                                                                     \
        asm volatile("cp.async.commit_group;");                               \
    } while (0)

    // Prologue: stages 0..NS-2
#pragma unroll
    for (int t = 0; t < NS - 1; t++) LOAD_STAGE(t);

    for (int kt = 0; kt < KT; kt++) {
        asm volatile("cp.async.wait_group %0;" :: "n"(NS - 2));
        __syncthreads();
        if (kt + NS - 1 < KT) {
            LOAD_STAGE(kt + NS - 1);
        } else {
            asm volatile("cp.async.commit_group;");
        }

        const uint32_t sb = sbase + (kt & (NS - 1)) * STAGE_BYTES;
        const uint32_t aB = sb + 0 * TILE_BYTES;
        const uint32_t bB = sb + 1 * TILE_BYTES;

#pragma unroll
        for (int ks = 0; ks < 2; ks++) {
            uint32_t af[4][4];
#pragma unroll
            for (int mt = 0; mt < 4; mt++) ldsm4(af[mt], aB + aoff[ks][mt]);
#pragma unroll
            for (int np = 0; np < 4; np++) {
                uint32_t bf[4];
                ldsm4(bf, bB + boff[ks][np]);
#pragma unroll
                for (int mt = 0; mt < 4; mt++) {
                    mma16816(acc[mt][np * 2 + 0], af[mt], bf[0], bf[1]);
                    mma16816(acc[mt][np * 2 + 1], af[mt], bf[2], bf[3]);
                }
            }
        }
    }
#undef LOAD_STAGE

    // Epilogue: + bias, fp32 out, streaming float2 stores
#pragma unroll
    for (int mt = 0; mt < 4; mt++) {
#pragma unroll
        for (int nt = 0; nt < 8; nt++) {
            const int row = m0 + wm * 64 + mt * 16 + (lane >> 2);
            const int col = n0 + wn * 64 + nt * 8 + (lane & 3) * 2;
            const float b0 = bias[col], b1 = bias[col + 1];
            float2 v0 = {acc[mt][nt][0] + b0, acc[mt][nt][1] + b1};
            float2 v1 = {acc[mt][nt][2] + b0, acc[mt][nt][3] + b1};
            __stcs((float2*)(out + (size_t)row * O_DIM + col), v0);
            __stcs((float2*)(out + (size_t)(row + 8) * O_DIM + col), v1);
        }
    }
}

// ---------------------------------------------------------------------------
extern "C" void kernel_launch(void* const* d_in, const int* in_sizes, int n_in,
                              void* d_out, int out_size) {
    const int*   qweight   = (const int*)d_in[0];
    const float* scales    = (const float*)d_in[1];
    const float* lora_up   = (const float*)d_in[2];
    const float* lora_down = (const float*)d_in[3];
    const float* bias      = (const float*)d_in[4];
    const float* x         = (const float*)d_in[5];
    float* out = (float*)d_out;

    prep_fused<<<O_DIM + XBLK, 256>>>(qweight, scales, lora_up, lora_down, x);

    cudaFuncSetAttribute(gemm_fp16,
                         cudaFuncAttributeMaxDynamicSharedMemorySize, SMEM_BYTES);
    dim3 grid(O_DIM / BN, M_DIM / BM);  // (32, 128)
    gemm_fp16<<<grid, NTHREADS, SMEM_BYTES>>>(bias, out);
}